// round 12
// baseline (speedup 1.0000x reference)
#include <cuda_runtime.h>
#include <cstdint>

#define NC 1024
#define DY 16
#define G  256
#define M  2
#define CH 64
#define NT 16                    // tiles per dim
#define NTILES (M * NT * NT)     // 512
#define XTOT (M * G * G * 2)
#define ZTOT (M * G * G * 17)
#define MAXU (NTILES * 16)       // 8192 max units
#define GRIDU 2048

typedef unsigned long long u64;

// TRANSPOSED axis weights: g_W[axis][m][c][i]  (i contiguous)
__device__ float g_W[2][M][NC][G];            // 4 MB
__device__ int   g_len[M][NT][NT];
__device__ int   g_list[M][NT][NT][NC];       // 2 MB
__device__ int   g_units[MAXU];               // (tile<<4)|chunk
__device__ int   g_nunits;

// ---- packed f32x2 helpers ----
__device__ __forceinline__ u64 pack2(float lo, float hi) {
    u64 r; asm("mov.b64 %0, {%1, %2};" : "=l"(r) : "f"(lo), "f"(hi)); return r;
}
__device__ __forceinline__ void unpack2(float& lo, float& hi, u64 v) {
    asm("mov.b64 {%0, %1}, %2;" : "=f"(lo), "=f"(hi) : "l"(v));
}
__device__ __forceinline__ void ffma2(u64& d, u64 a, u64 b) {
    asm("fma.rn.f32x2 %0, %1, %2, %0;" : "+l"(d) : "l"(a), "l"(b));
}
__device__ __forceinline__ void lds_v2_f32(float& a, float& b, uint32_t addr) {
    asm volatile("ld.shared.v2.f32 {%0, %1}, [%2];" : "=f"(a), "=f"(b) : "r"(addr));
}
__device__ __forceinline__ void cpasync16(uint32_t dst, const void* src, int src_bytes) {
    asm volatile("cp.async.cg.shared.global [%0], [%1], 16, %2;"
                 :: "r"(dst), "l"(src), "r"(src_bytes));
}
__device__ __forceinline__ void cpasync_commit() {
    asm volatile("cp.async.commit_group;");
}
template <int N>
__device__ __forceinline__ void cpasync_wait() {
    asm volatile("cp.async.wait_group %0;" :: "n"(N));
}

// ---------------------------------------------------------------------------
// Kernel 1: init output — x_grid coords + zero the z region (REDs accumulate)
// ---------------------------------------------------------------------------
__global__ void init_kernel(float* __restrict__ out) {
    int idx = blockIdx.x * blockDim.x + threadIdx.x;   // XTOT + ZTOT
    if (idx < XTOT) {
        int d = idx & 1;
        int j = (idx >> 1) & (G - 1);
        int i = (idx >> 9) & (G - 1);
        int v = d ? j : i;
        out[idx] = 1.0f + (float)(v - 128) * (1.0f / 64.0f);
    } else {
        out[idx] = 0.0f;
    }
}

// ---------------------------------------------------------------------------
// Kernel 2: build Wx/Wy transposed; warp-uniform MUFU skip for far entries
// ---------------------------------------------------------------------------
__global__ void weights_kernel(const float* __restrict__ xc,
                               const float* __restrict__ lsp) {
    int idx = blockIdx.x * blockDim.x + threadIdx.x;   // 1,048,576
    int i = idx & (G - 1);
    int c = (idx >> 8) & (NC - 1);
    int d = (idx >> 18) & 1;
    int m = idx >> 19;
    float l = 1e-5f + log1pf(expf(lsp[d]));            // exact softplus
    float rl = 1.0f / l;
    float g = 1.0f + (float)(i - 128) * (1.0f / 64.0f);
    float x = xc[(m * NC + c) * 2 + d];
    float t = (g - x) * rl;
    float t2 = t * t;
    float w = 0.0f;
    bool keep = t2 <= 27.63f;
    if (__any_sync(0xffffffffu, keep)) {
        if (keep) w = __expf(-0.5f * t2);
    }
    g_W[d][m][c][i] = w;
}

// ---------------------------------------------------------------------------
// Kernel 3: per-tile c-list compaction (one warp per tile, deterministic)
// ---------------------------------------------------------------------------
__global__ void compact_kernel(const float* __restrict__ xc,
                               const float* __restrict__ lsp) {
    int warp = (blockIdx.x * blockDim.x + threadIdx.x) >> 5;
    int lane = threadIdx.x & 31;
    if (warp >= NTILES) return;
    int jT = warp & (NT - 1);
    int iT = (warp >> 4) & (NT - 1);
    int m  = warp >> 8;

    float rlx = 1.0f / (1e-5f + log1pf(expf(lsp[0])));
    float rly = 1.0f / (1e-5f + log1pf(expf(lsp[1])));
    float x0 = 1.0f + (float)(iT * 16 - 128) * (1.0f / 64.0f);
    float x1 = x0 + 15.0f / 64.0f;
    float y0 = 1.0f + (float)(jT * 16 - 128) * (1.0f / 64.0f);
    float y1 = y0 + 15.0f / 64.0f;
    const float thr = 27.63f;   // weight cutoff ~1e-6

    int count = 0;
    int* lst = g_list[m][iT][jT];
    for (int c0 = 0; c0 < NC; c0 += 32) {
        int c = c0 + lane;
        float cx = xc[(m * NC + c) * 2 + 0];
        float cy = xc[(m * NC + c) * 2 + 1];
        float dx = fmaxf(fmaxf(x0 - cx, cx - x1), 0.0f) * rlx;
        float dy = fmaxf(fmaxf(y0 - cy, cy - y1), 0.0f) * rly;
        bool keep = (dx * dx + dy * dy) <= thr;
        unsigned mask = __ballot_sync(0xffffffffu, keep);
        int off = __popc(mask & ((1u << lane) - 1u));
        if (keep) lst[count + off] = c;
        count += __popc(mask);
    }
    if (lane == 0) g_len[m][iT][jT] = count;
}

// ---------------------------------------------------------------------------
// Kernel 4: build uniform work units. 1 CTA, 512 threads; inclusive scan of
// nchunk = ceil(len/64), then each thread emits its (tile, chunk) entries.
// ---------------------------------------------------------------------------
__global__ void units_kernel() {
    __shared__ int s[NTILES];
    int t = threadIdx.x;
    int len = ((const int*)g_len)[t];
    int n = (len + CH - 1) / CH;
    s[t] = n;
    __syncthreads();
    for (int off = 1; off < NTILES; off <<= 1) {
        int v = (t >= off) ? s[t - off] : 0;
        __syncthreads();
        s[t] += v;
        __syncthreads();
    }
    int base = s[t] - n;
    for (int k = 0; k < n; k++) g_units[base + k] = (t << 4) | k;
    if (t == NTILES - 1) g_nunits = s[t];
}

// ---------------------------------------------------------------------------
// Kernel 5: uniform-unit contraction. One unit = 64 c-entries of one tile.
// Thread = (2i x 2j x 4k); results RED-accumulated into d_out.
// ---------------------------------------------------------------------------
__global__ __launch_bounds__(256, 4)
void setconv_unit(const float* __restrict__ yc, float* __restrict__ out) {
    __shared__ float  wxs[CH][16];
    __shared__ float  wys[CH][16];
    __shared__ float4 ycs[CH][4];

    const int tid = threadIdx.x;
    const int tj2 = tid & 7;
    const int ti2 = (tid >> 3) & 7;
    const int tk  = tid >> 6;           // 0..3
    const int scc = tid >> 2;
    const int sq  = tid & 3;
    const uint32_t wxs_s = (uint32_t)__cvta_generic_to_shared(&wxs[0][0]);
    const uint32_t wys_s = (uint32_t)__cvta_generic_to_shared(&wys[0][0]);
    const uint32_t ycs_s = (uint32_t)__cvta_generic_to_shared(&ycs[0][0]);
    const uint32_t sdoff = (uint32_t)(scc * 16 + sq * 4) * 4;
    const float4* __restrict__ yc4 = (const float4*)yc;

    const int nu = g_nunits;
    float* outZ = out + (size_t)XTOT;

    for (int ub = blockIdx.x; ub < nu; ub += GRIDU) {
        const int u = g_units[ub];
        const int tile = u >> 4;
        const int chunk = u & 15;
        const int jT = tile & (NT - 1);
        const int iT = (tile >> 4) & (NT - 1);
        const int m  = tile >> 8;
        const int iBase = iT * 16;
        const int jBase = jT * 16;
        const int len = g_len[m][iT][jT];
        const int* __restrict__ lst = g_list[m][iT][jT];
        const int c0 = chunk * CH;

        // --- stage (zero-filled past len) ---
        {
            int cpos = c0 + scc;
            bool valid = cpos < len;
            int cidx = valid ? lst[cpos] : 0;
            int b16 = valid ? 16 : 0;
            cpasync16(wxs_s + sdoff, &g_W[0][m][cidx][iBase + sq * 4], b16);
            cpasync16(wys_s + sdoff, &g_W[1][m][cidx][jBase + sq * 4], b16);
            cpasync16(ycs_s + sdoff, &yc4[((m * NC + cidx) << 2) + sq], b16);
            cpasync_commit();
        }
        cpasync_wait<0>();
        __syncthreads();

        u64 acc2[4][2];
#pragma unroll
        for (int a = 0; a < 4; a++) { acc2[a][0] = 0ull; acc2[a][1] = 0ull; }
        float accD[4] = {0.0f, 0.0f, 0.0f, 0.0f};

        const uint32_t wx_a = wxs_s + (uint32_t)ti2 * 8;
        const uint32_t wy_a = wys_s + (uint32_t)tj2 * 8;
        const uint32_t yc_a = ycs_s + (uint32_t)tk * 16;

        if (tk == 3) {
#pragma unroll 8
            for (int cc = 0; cc < CH; ++cc) {
                float wx0, wx1, wy0, wy1;
                lds_v2_f32(wx0, wx1, wx_a + cc * 64);
                lds_v2_f32(wy0, wy1, wy_a + cc * 64);
                u64 y01, y23;
                asm volatile("ld.shared.v2.b64 {%0, %1}, [%2];"
                             : "=l"(y01), "=l"(y23) : "r"(yc_a + cc * 64));
                float w00 = wx0 * wy0, w01 = wx0 * wy1;
                float w10 = wx1 * wy0, w11 = wx1 * wy1;
                accD[0] += w00; accD[1] += w01; accD[2] += w10; accD[3] += w11;
                u64 p00 = pack2(w00, w00), p01 = pack2(w01, w01);
                u64 p10 = pack2(w10, w10), p11 = pack2(w11, w11);
                ffma2(acc2[0][0], p00, y01); ffma2(acc2[0][1], p00, y23);
                ffma2(acc2[1][0], p01, y01); ffma2(acc2[1][1], p01, y23);
                ffma2(acc2[2][0], p10, y01); ffma2(acc2[2][1], p10, y23);
                ffma2(acc2[3][0], p11, y01); ffma2(acc2[3][1], p11, y23);
            }
        } else {
#pragma unroll 8
            for (int cc = 0; cc < CH; ++cc) {
                float wx0, wx1, wy0, wy1;
                lds_v2_f32(wx0, wx1, wx_a + cc * 64);
                lds_v2_f32(wy0, wy1, wy_a + cc * 64);
                u64 y01, y23;
                asm volatile("ld.shared.v2.b64 {%0, %1}, [%2];"
                             : "=l"(y01), "=l"(y23) : "r"(yc_a + cc * 64));
                float w00 = wx0 * wy0, w01 = wx0 * wy1;
                float w10 = wx1 * wy0, w11 = wx1 * wy1;
                u64 p00 = pack2(w00, w00), p01 = pack2(w01, w01);
                u64 p10 = pack2(w10, w10), p11 = pack2(w11, w11);
                ffma2(acc2[0][0], p00, y01); ffma2(acc2[0][1], p00, y23);
                ffma2(acc2[1][0], p01, y01); ffma2(acc2[1][1], p01, y23);
                ffma2(acc2[2][0], p10, y01); ffma2(acc2[2][1], p10, y23);
                ffma2(acc2[3][0], p11, y01); ffma2(acc2[3][1], p11, y23);
            }
        }
        __syncthreads();   // smem reusable next unit

        // --- RED-accumulate into output ---
#pragma unroll
        for (int di = 0; di < 2; di++) {
#pragma unroll
            for (int dj = 0; dj < 2; dj++) {
                int ij = di * 2 + dj;
                int i = iBase + ti2 * 2 + di;
                int j = jBase + tj2 * 2 + dj;
                float* zo = outZ + ((size_t)((m * G + i) * G + j)) * 17 + tk * 4;
                float a0, a1, a2, a3;
                unpack2(a0, a1, acc2[ij][0]);
                unpack2(a2, a3, acc2[ij][1]);
                atomicAdd(zo + 0, a0);
                atomicAdd(zo + 1, a1);
                atomicAdd(zo + 2, a2);
                atomicAdd(zo + 3, a3);
                if (tk == 3) atomicAdd(zo + 4, accD[ij]);
            }
        }
    }
}

// ---------------------------------------------------------------------------
extern "C" void kernel_launch(void* const* d_in, const int* in_sizes, int n_in,
                              void* d_out, int out_size) {
    const float* xc  = (const float*)d_in[0];  // [2,1024,2]
    const float* yc  = (const float*)d_in[1];  // [2,1024,16]
    const float* lsp = (const float*)d_in[3];  // [2]
    float* out = (float*)d_out;

    init_kernel<<<(XTOT + ZTOT) / 256, 256>>>(out);
    weights_kernel<<<(M * 2 * G * NC) / 256, 256>>>(xc, lsp);
    compact_kernel<<<(NTILES * 32) / 256, 256>>>(xc, lsp);
    units_kernel<<<1, NTILES>>>();
    setconv_unit<<<GRIDU, 256>>>(yc, out);
}

// round 13
// speedup vs baseline: 1.0425x; 1.0425x over previous
#include <cuda_runtime.h>
#include <cstdint>

#define NC 1024
#define DY 16
#define G  256
#define M  2
#define CH 64
#define NT 16                    // tiles per dim
#define NTILES (M * NT * NT)     // 512
#define XTOT (M * G * G * 2)

typedef unsigned long long u64;

// TRANSPOSED axis weights: g_W[axis][m][c][i]  (i contiguous)
__device__ float g_W[2][M][NC][G];            // 4 MB
__device__ int   g_len[M][NT][NT];
__device__ int   g_list[M][NT][NT][NC];       // 2 MB

// ---- packed f32x2 helpers ----
__device__ __forceinline__ u64 pack2(float lo, float hi) {
    u64 r; asm("mov.b64 %0, {%1, %2};" : "=l"(r) : "f"(lo), "f"(hi)); return r;
}
__device__ __forceinline__ void unpack2(float& lo, float& hi, u64 v) {
    asm("mov.b64 {%0, %1}, %2;" : "=f"(lo), "=f"(hi) : "l"(v));
}
__device__ __forceinline__ void ffma2(u64& d, u64 a, u64 b) {
    asm("fma.rn.f32x2 %0, %1, %2, %0;" : "+l"(d) : "l"(a), "l"(b));
}
__device__ __forceinline__ void lds_v2_f32(float& a, float& b, uint32_t addr) {
    asm volatile("ld.shared.v2.f32 {%0, %1}, [%2];" : "=f"(a), "=f"(b) : "r"(addr));
}
__device__ __forceinline__ void cpasync16(uint32_t dst, const void* src, int src_bytes) {
    asm volatile("cp.async.cg.shared.global [%0], [%1], 16, %2;"
                 :: "r"(dst), "l"(src), "r"(src_bytes));
}
__device__ __forceinline__ void cpasync_commit() {
    asm volatile("cp.async.commit_group;");
}
template <int N>
__device__ __forceinline__ void cpasync_wait() {
    asm volatile("cp.async.wait_group %0;" :: "n"(N));
}

// ---------------------------------------------------------------------------
// Kernel 1: build Wx/Wy transposed; warp-uniform MUFU skip for far entries
// (t^2 > 27.63 -> w = 0; same cutoff as compaction, so consistent)
// ---------------------------------------------------------------------------
__global__ void weights_kernel(const float* __restrict__ xc,
                               const float* __restrict__ lsp) {
    int idx = blockIdx.x * blockDim.x + threadIdx.x;   // 1,048,576
    int i = idx & (G - 1);
    int c = (idx >> 8) & (NC - 1);
    int d = (idx >> 18) & 1;
    int m = idx >> 19;
    float l = 1e-5f + log1pf(expf(lsp[d]));            // exact softplus
    float rl = 1.0f / l;
    float g = 1.0f + (float)(i - 128) * (1.0f / 64.0f);
    float x = xc[(m * NC + c) * 2 + d];
    float t = (g - x) * rl;
    float t2 = t * t;
    float w = 0.0f;
    bool keep = t2 <= 27.63f;
    if (__any_sync(0xffffffffu, keep)) {
        if (keep) w = __expf(-0.5f * t2);
    }
    g_W[d][m][c][i] = w;
}

// ---------------------------------------------------------------------------
// Kernel 2: per-tile c-list compaction (one warp per tile, deterministic)
// ---------------------------------------------------------------------------
__global__ void compact_kernel(const float* __restrict__ xc,
                               const float* __restrict__ lsp) {
    int warp = (blockIdx.x * blockDim.x + threadIdx.x) >> 5;
    int lane = threadIdx.x & 31;
    if (warp >= NTILES) return;
    int jT = warp & (NT - 1);
    int iT = (warp >> 4) & (NT - 1);
    int m  = warp >> 8;

    float rlx = 1.0f / (1e-5f + log1pf(expf(lsp[0])));
    float rly = 1.0f / (1e-5f + log1pf(expf(lsp[1])));
    float x0 = 1.0f + (float)(iT * 16 - 128) * (1.0f / 64.0f);
    float x1 = x0 + 15.0f / 64.0f;
    float y0 = 1.0f + (float)(jT * 16 - 128) * (1.0f / 64.0f);
    float y1 = y0 + 15.0f / 64.0f;
    const float thr = 27.63f;   // weight cutoff ~1e-6

    int count = 0;
    int* lst = g_list[m][iT][jT];
    for (int c0 = 0; c0 < NC; c0 += 32) {
        int c = c0 + lane;
        float cx = xc[(m * NC + c) * 2 + 0];
        float cy = xc[(m * NC + c) * 2 + 1];
        float dx = fmaxf(fmaxf(x0 - cx, cx - x1), 0.0f) * rlx;
        float dy = fmaxf(fmaxf(y0 - cy, cy - y1), 0.0f) * rly;
        bool keep = (dx * dx + dy * dy) <= thr;
        unsigned mask = __ballot_sync(0xffffffffu, keep);
        int off = __popc(mask & ((1u << lane) - 1u));
        if (keep) lst[count + off] = c;
        count += __popc(mask);
    }
    if (lane == 0) g_len[m][iT][jT] = count;
}

// ---------------------------------------------------------------------------
// Kernel 3: 16x16-tile contraction; 512 threads, thread = (2i x 1j x 4k).
// tid = tk*128 + ti2*16 + tj.  Low accumulator count -> deep LDS pipelining.
// tk==3 also carries density. Grid coords folded into the same kernel.
// ---------------------------------------------------------------------------
__global__ __launch_bounds__(512, 2)
void setconv_kernel(const float* __restrict__ yc, float* __restrict__ out) {
    __shared__ float  wxs[2][CH][16];   // [buf][c][i]   8 KB
    __shared__ float  wys[2][CH][16];   // [buf][c][j]   8 KB
    __shared__ float4 ycs[2][CH][4];    // [buf][c][k/4] 8 KB

    const int tile = blockIdx.x;
    const int jT = tile & (NT - 1);
    const int iT = (tile >> 4) & (NT - 1);
    const int m  = tile >> 8;
    const int tid = threadIdx.x;
    const int tj  = tid & 15;
    const int ti2 = (tid >> 4) & 7;
    const int tk  = tid >> 7;           // 0..3, uniform per warp
    const int iBase = iT * 16;
    const int jBase = jT * 16;
    const int i0 = iBase + ti2 * 2;
    const int j  = jBase + tj;

    // x_grid_b coords (tk==0 threads: 2 positions each -> full 16x16 tile)
    if (tk == 0) {
#pragma unroll
        for (int di = 0; di < 2; di++) {
            float2 g2;
            g2.x = 1.0f + (float)(i0 + di - 128) * (1.0f / 64.0f);
            g2.y = 1.0f + (float)(j - 128) * (1.0f / 64.0f);
            ((float2*)out)[(size_t)(m * G + i0 + di) * G + j] = g2;
        }
    }

    const int len = g_len[m][iT][jT];
    float* outZ = out + (size_t)XTOT;

    if (len == 0) {
#pragma unroll
        for (int di = 0; di < 2; di++) {
            float* zo = outZ + ((size_t)((m * G + i0 + di) * G + j)) * 17 + tk * 4;
            zo[0] = 0.0f; zo[1] = 0.0f; zo[2] = 0.0f; zo[3] = 0.0f;
            if (tk == 3) zo[4] = 0.0f;
        }
        return;
    }

    const int* __restrict__ lst = g_list[m][iT][jT];
    const float4* __restrict__ yc4 = (const float4*)yc;

    const uint32_t wxs_s = (uint32_t)__cvta_generic_to_shared(&wxs[0][0][0]);
    const uint32_t wys_s = (uint32_t)__cvta_generic_to_shared(&wys[0][0][0]);
    const uint32_t ycs_s = (uint32_t)__cvta_generic_to_shared(&ycs[0][0][0]);

    // staging: threads 0..255 -> wx + yc unit (cc=tid>>2, q=tid&3);
    //          threads 256..511 -> wy unit.
    const int scc = (tid & 255) >> 2;
    const int sq  = tid & 3;
    const uint32_t sdoff = (uint32_t)(scc * 16 + sq * 4) * 4;
    const bool grpA = tid < 256;

    const int nchunk = (len + CH - 1) / CH;

    auto stage = [&](int buf, int c0) {
        int cpos = c0 + scc;
        bool valid = cpos < len;
        int cidx = valid ? lst[cpos] : 0;
        int b16 = valid ? 16 : 0;
        uint32_t boff = (uint32_t)buf * (CH * 16 * 4);
        if (grpA) {
            cpasync16(wxs_s + boff + sdoff, &g_W[0][m][cidx][iBase + sq * 4], b16);
            cpasync16(ycs_s + boff + sdoff, &yc4[((m * NC + cidx) << 2) + sq], b16);
        } else {
            cpasync16(wys_s + boff + sdoff, &g_W[1][m][cidx][jBase + sq * 4], b16);
        }
        cpasync_commit();
    };

    u64 accA0 = 0ull, accA1 = 0ull;   // i0,   k pair 0/1
    u64 accB0 = 0ull, accB1 = 0ull;   // i0+1, k pair 0/1
    float accD0 = 0.0f, accD1 = 0.0f;

    stage(0, 0);

    for (int t = 0; t < nchunk; t++) {
        int cur = t & 1;
        if (t + 1 < nchunk) {
            stage(cur ^ 1, (t + 1) * CH);
            cpasync_wait<1>();
        } else {
            cpasync_wait<0>();
        }
        __syncthreads();

        const uint32_t bo = (uint32_t)cur * (CH * 16 * 4);
        const uint32_t wx_a = wxs_s + bo + (uint32_t)ti2 * 8;
        const uint32_t wy_a = wys_s + bo + (uint32_t)tj * 4;
        const uint32_t yc_a = ycs_s + bo + (uint32_t)tk * 16;

        if (tk == 3) {
#pragma unroll 8
            for (int cc = 0; cc < CH; ++cc) {
                float wx0, wx1, wy;
                lds_v2_f32(wx0, wx1, wx_a + cc * 64);
                asm volatile("ld.shared.f32 %0, [%1];" : "=f"(wy) : "r"(wy_a + cc * 64));
                u64 y01, y23;
                asm volatile("ld.shared.v2.b64 {%0, %1}, [%2];"
                             : "=l"(y01), "=l"(y23) : "r"(yc_a + cc * 64));
                float w0 = wx0 * wy, w1 = wx1 * wy;
                accD0 += w0; accD1 += w1;
                u64 p0 = pack2(w0, w0), p1 = pack2(w1, w1);
                ffma2(accA0, p0, y01); ffma2(accA1, p0, y23);
                ffma2(accB0, p1, y01); ffma2(accB1, p1, y23);
            }
        } else {
#pragma unroll 8
            for (int cc = 0; cc < CH; ++cc) {
                float wx0, wx1, wy;
                lds_v2_f32(wx0, wx1, wx_a + cc * 64);
                asm volatile("ld.shared.f32 %0, [%1];" : "=f"(wy) : "r"(wy_a + cc * 64));
                u64 y01, y23;
                asm volatile("ld.shared.v2.b64 {%0, %1}, [%2];"
                             : "=l"(y01), "=l"(y23) : "r"(yc_a + cc * 64));
                float w0 = wx0 * wy, w1 = wx1 * wy;
                u64 p0 = pack2(w0, w0), p1 = pack2(w1, w1);
                ffma2(accA0, p0, y01); ffma2(accA1, p0, y23);
                ffma2(accB0, p1, y01); ffma2(accB1, p1, y23);
            }
        }
        __syncthreads();
    }

    // --- epilogue: 2 positions x 4 channels (+density for tk==3) ---
    {
        float a0, a1, a2, a3;
        float* zo = outZ + ((size_t)((m * G + i0) * G + j)) * 17 + tk * 4;
        unpack2(a0, a1, accA0); unpack2(a2, a3, accA1);
        zo[0] = a0; zo[1] = a1; zo[2] = a2; zo[3] = a3;
        if (tk == 3) zo[4] = accD0;

        float* zo1 = outZ + ((size_t)((m * G + i0 + 1) * G + j)) * 17 + tk * 4;
        unpack2(a0, a1, accB0); unpack2(a2, a3, accB1);
        zo1[0] = a0; zo1[1] = a1; zo1[2] = a2; zo1[3] = a3;
        if (tk == 3) zo1[4] = accD1;
    }
}

// ---------------------------------------------------------------------------
extern "C" void kernel_launch(void* const* d_in, const int* in_sizes, int n_in,
                              void* d_out, int out_size) {
    const float* xc  = (const float*)d_in[0];  // [2,1024,2]
    const float* yc  = (const float*)d_in[1];  // [2,1024,16]
    const float* lsp = (const float*)d_in[3];  // [2]
    float* out = (float*)d_out;

    weights_kernel<<<(M * 2 * G * NC) / 256, 256>>>(xc, lsp);
    compact_kernel<<<(NTILES * 32) / 256, 256>>>(xc, lsp);
    setconv_kernel<<<NTILES, 512>>>(yc, out);
}

// round 15
// speedup vs baseline: 1.0873x; 1.0430x over previous
#include <cuda_runtime.h>
#include <cstdint>

#define NC 1024
#define G  256
#define M  2
#define CH 64
#define NTI 16                   // i-tiles (16 rows each)
#define NTJ 32                   // j-tiles (8 cols each)
#define XTOT (M * G * G * 2)

typedef unsigned long long u64;

// TRANSPOSED axis weights: g_W[axis][m][c][i]  (i contiguous)
__device__ float g_W[2][M][NC][G];             // 4 MB
__device__ int   g_len[M][NTI][NTJ];
__device__ int   g_list[M][NTI][NTJ][NC];      // 4 MB

// ---- packed f32x2 helpers ----
__device__ __forceinline__ u64 pack2(float lo, float hi) {
    u64 r; asm("mov.b64 %0, {%1, %2};" : "=l"(r) : "f"(lo), "f"(hi)); return r;
}
__device__ __forceinline__ void unpack2(float& lo, float& hi, u64 v) {
    asm("mov.b64 {%0, %1}, %2;" : "=f"(lo), "=f"(hi) : "l"(v));
}
__device__ __forceinline__ void ffma2(u64& d, u64 a, u64 b) {
    asm("fma.rn.f32x2 %0, %1, %2, %0;" : "+l"(d) : "l"(a), "l"(b));
}
__device__ __forceinline__ void cpasync16(uint32_t dst, const void* src, int src_bytes) {
    asm volatile("cp.async.cg.shared.global [%0], [%1], 16, %2;"
                 :: "r"(dst), "l"(src), "r"(src_bytes));
}
__device__ __forceinline__ void cpasync_commit() {
    asm volatile("cp.async.commit_group;");
}
template <int N>
__device__ __forceinline__ void cpasync_wait() {
    asm volatile("cp.async.wait_group %0;" :: "n"(N));
}

// ---------------------------------------------------------------------------
// Kernel 1: build Wx/Wy transposed (plain __expf; skip variant was slower)
// ---------------------------------------------------------------------------
__global__ void weights_kernel(const float* __restrict__ xc,
                               const float* __restrict__ lsp) {
    int idx = blockIdx.x * blockDim.x + threadIdx.x;   // 1,048,576
    int i = idx & (G - 1);
    int c = (idx >> 8) & (NC - 1);
    int d = (idx >> 18) & 1;
    int m = idx >> 19;
    float l = 1e-5f + log1pf(expf(lsp[d]));            // exact softplus
    float rl = 1.0f / l;
    float g = 1.0f + (float)(i - 128) * (1.0f / 64.0f);
    float x = xc[(m * NC + c) * 2 + d];
    float t = (g - x) * rl;
    g_W[d][m][c][i] = __expf(-0.5f * t * t);
}

// ---------------------------------------------------------------------------
// Kernel 2: per-halftile c-list compaction (one warp per 16x8 tile)
// ---------------------------------------------------------------------------
__global__ void compact_kernel(const float* __restrict__ xc,
                               const float* __restrict__ lsp) {
    int warp = (blockIdx.x * blockDim.x + threadIdx.x) >> 5;
    int lane = threadIdx.x & 31;
    if (warp >= M * NTI * NTJ) return;
    int jT = warp & (NTJ - 1);
    int iT = (warp >> 5) & (NTI - 1);
    int m  = warp >> 9;

    float rlx = 1.0f / (1e-5f + log1pf(expf(lsp[0])));
    float rly = 1.0f / (1e-5f + log1pf(expf(lsp[1])));
    float x0 = 1.0f + (float)(iT * 16 - 128) * (1.0f / 64.0f);
    float x1 = x0 + 15.0f / 64.0f;
    float y0 = 1.0f + (float)(jT * 8 - 128) * (1.0f / 64.0f);
    float y1 = y0 + 7.0f / 64.0f;
    const float thr = 27.63f;   // weight cutoff ~1e-6

    int count = 0;
    int* lst = g_list[m][iT][jT];
    for (int c0 = 0; c0 < NC; c0 += 32) {
        int c = c0 + lane;
        float cx = xc[(m * NC + c) * 2 + 0];
        float cy = xc[(m * NC + c) * 2 + 1];
        float dx = fmaxf(fmaxf(x0 - cx, cx - x1), 0.0f) * rlx;
        float dy = fmaxf(fmaxf(y0 - cy, cy - y1), 0.0f) * rly;
        bool keep = (dx * dx + dy * dy) <= thr;
        unsigned mask = __ballot_sync(0xffffffffu, keep);
        int off = __popc(mask & ((1u << lane) - 1u));
        if (keep) lst[count + off] = c;
        count += __popc(mask);
    }
    if (lane == 0) g_len[m][iT][jT] = count;
}

// ---------------------------------------------------------------------------
// Kernel 3: 16x8 half-tile contraction, 3-stage cp.async pipeline.
// 256 threads: tj = tid&7, ti = (tid>>3)&15, kq = tid>>7 (channels kq*8..+7;
// kq==1 also carries density -> channel 16). Grid coords folded in.
// ---------------------------------------------------------------------------
__global__ __launch_bounds__(256, 4)
void setconv_kernel(const float* __restrict__ yc, float* __restrict__ out) {
    __shared__ float wxs[3][CH][16];   // 12 KB
    __shared__ float wys[3][CH][8];    //  6 KB
    __shared__ float ycs[3][CH][16];   // 12 KB

    const int jT = blockIdx.x;
    const int iT = blockIdx.y;
    const int m  = blockIdx.z;
    const int tid = threadIdx.x;
    const int tj = tid & 7;
    const int ti = (tid >> 3) & 15;
    const int kq = tid >> 7;           // 0 or 1, uniform per warp
    const int iBase = iT * 16;
    const int jBase = jT * 8;
    const int i = iBase + ti, j = jBase + tj;

    // x_grid_b coords (kq==0 threads cover all 128 positions)
    if (kq == 0) {
        float2 g2;
        g2.x = 1.0f + (float)(i - 128) * (1.0f / 64.0f);
        g2.y = 1.0f + (float)(j - 128) * (1.0f / 64.0f);
        ((float2*)out)[(size_t)(m * G + i) * G + j] = g2;
    }

    const int len = g_len[m][iT][jT];
    float* zo = out + (size_t)XTOT + ((size_t)((m * G + i) * G + j)) * 17 + kq * 8;

    if (len == 0) {
#pragma unroll
        for (int k = 0; k < 8; k++) zo[k] = 0.0f;
        if (kq == 1) zo[8] = 0.0f;
        return;
    }

    const int* __restrict__ lst = g_list[m][iT][jT];
    const float4* __restrict__ yc4 = (const float4*)yc;

    const uint32_t wxs_s = (uint32_t)__cvta_generic_to_shared(&wxs[0][0][0]);
    const uint32_t wys_s = (uint32_t)__cvta_generic_to_shared(&wys[0][0][0]);
    const uint32_t ycs_s = (uint32_t)__cvta_generic_to_shared(&ycs[0][0][0]);

    const int nchunk = (len + CH - 1) / CH;

    // staging: wx 256 quads (all threads), wy 128 quads (tid<128),
    //          yc 256 quads (tid>=128 take 2 each)
    auto stage = [&](int buf, int c0) {
        {   // wx: cc = tid>>2, q = tid&3
            int cc = tid >> 2, q = tid & 3;
            int cpos = c0 + cc;
            bool v = cpos < len;
            int cidx = v ? lst[cpos] : 0;
            cpasync16(wxs_s + (uint32_t)(buf * 4096 + (cc * 16 + q * 4) * 4),
                      &g_W[0][m][cidx][iBase + q * 4], v ? 16 : 0);
        }
        if (tid < 128) {   // wy: cc = tid>>1, q = tid&1
            int cc = tid >> 1, q = tid & 1;
            int cpos = c0 + cc;
            bool v = cpos < len;
            int cidx = v ? lst[cpos] : 0;
            cpasync16(wys_s + (uint32_t)(buf * 2048 + (cc * 8 + q * 4) * 4),
                      &g_W[1][m][cidx][jBase + q * 4], v ? 16 : 0);
        } else {           // yc: two quads per thread
            int t2 = tid - 128;
            int cc = t2 >> 1, qb = (t2 & 1) * 2;
            int cpos = c0 + cc;
            bool v = cpos < len;
            int cidx = v ? lst[cpos] : 0;
            const float4* src = &yc4[((m * NC + cidx) << 2) + qb];
            uint32_t dst = ycs_s + (uint32_t)(buf * 4096 + (cc * 16 + qb * 4) * 4);
            cpasync16(dst,      src,     v ? 16 : 0);
            cpasync16(dst + 16, src + 1, v ? 16 : 0);
        }
        cpasync_commit();
    };

    u64 acc0 = 0ull, acc1 = 0ull, acc2v = 0ull, acc3 = 0ull;
    float accD = 0.0f;

    stage(0, 0);
    if (nchunk > 1) stage(1, CH);

    for (int t = 0; t < nchunk; t++) {
        if (t + 2 < nchunk) {
            stage((t + 2) % 3, (t + 2) * CH);
            cpasync_wait<2>();
        } else if (t + 1 < nchunk) {
            cpasync_wait<1>();
        } else {
            cpasync_wait<0>();
        }
        __syncthreads();

        const int buf = t % 3;
        const uint32_t wx_a = wxs_s + (uint32_t)(buf * 4096) + (uint32_t)ti * 4;
        const uint32_t wy_a = wys_s + (uint32_t)(buf * 2048) + (uint32_t)tj * 4;
        const uint32_t yc_a = ycs_s + (uint32_t)(buf * 4096) + (uint32_t)kq * 32;

        if (kq == 1) {
#pragma unroll 8
            for (int cc = 0; cc < CH; ++cc) {
                float wx, wy;
                asm volatile("ld.shared.f32 %0, [%1];" : "=f"(wx) : "r"(wx_a + cc * 64));
                asm volatile("ld.shared.f32 %0, [%1];" : "=f"(wy) : "r"(wy_a + cc * 32));
                u64 y0, y1, y2, y3;
                asm volatile("ld.shared.v2.b64 {%0, %1}, [%2];"
                             : "=l"(y0), "=l"(y1) : "r"(yc_a + cc * 64));
                asm volatile("ld.shared.v2.b64 {%0, %1}, [%2];"
                             : "=l"(y2), "=l"(y3) : "r"(yc_a + cc * 64 + 16));
                float w = wx * wy;
                accD += w;
                u64 p = pack2(w, w);
                ffma2(acc0, p, y0); ffma2(acc1, p, y1);
                ffma2(acc2v, p, y2); ffma2(acc3, p, y3);
            }
        } else {
#pragma unroll 8
            for (int cc = 0; cc < CH; ++cc) {
                float wx, wy;
                asm volatile("ld.shared.f32 %0, [%1];" : "=f"(wx) : "r"(wx_a + cc * 64));
                asm volatile("ld.shared.f32 %0, [%1];" : "=f"(wy) : "r"(wy_a + cc * 32));
                u64 y0, y1, y2, y3;
                asm volatile("ld.shared.v2.b64 {%0, %1}, [%2];"
                             : "=l"(y0), "=l"(y1) : "r"(yc_a + cc * 64));
                asm volatile("ld.shared.v2.b64 {%0, %1}, [%2];"
                             : "=l"(y2), "=l"(y3) : "r"(yc_a + cc * 64 + 16));
                float w = wx * wy;
                u64 p = pack2(w, w);
                ffma2(acc0, p, y0); ffma2(acc1, p, y1);
                ffma2(acc2v, p, y2); ffma2(acc3, p, y3);
            }
        }
        __syncthreads();
    }

    // --- epilogue: 8 channels (+ density for kq==1) ---
    float a0, a1, a2, a3, a4, a5, a6, a7;
    unpack2(a0, a1, acc0); unpack2(a2, a3, acc1);
    unpack2(a4, a5, acc2v); unpack2(a6, a7, acc3);
    zo[0] = a0; zo[1] = a1; zo[2] = a2; zo[3] = a3;
    zo[4] = a4; zo[5] = a5; zo[6] = a6; zo[7] = a7;
    if (kq == 1) zo[8] = accD;
}

// ---------------------------------------------------------------------------
extern "C" void kernel_launch(void* const* d_in, const int* in_sizes, int n_in,
                              void* d_out, int out_size) {
    const float* xc  = (const float*)d_in[0];  // [2,1024,2]
    const float* yc  = (const float*)d_in[1];  // [2,1024,16]
    const float* lsp = (const float*)d_in[3];  // [2]
    float* out = (float*)d_out;

    weights_kernel<<<(M * 2 * G * NC) / 256, 256>>>(xc, lsp);
    compact_kernel<<<(M * NTI * NTJ * 32) / 256, 256>>>(xc, lsp);
    dim3 g(NTJ, NTI, M);
    setconv_kernel<<<g, 256>>>(yc, out);
}